// round 4
// baseline (speedup 1.0000x reference)
#include <cuda_runtime.h>
#include <math.h>

#define NB 4
#define NE 100000
#define NT 100000
#define ND 64
#define NBLK 120
#define NTHR 256
#define NTH_TOT (NBLK * NTHR)
#define HSZ 512          // hash: key -> support index
#define HSZ2 2048        // output accumulation hash
#define SUPN 256         // max distinct hop-1 entities
#define MAX1 4096
#define MAX2 8192
#define EPSV 1e-6f

// ---- persistent device state (re-initialized each launch in phase A) ----
__device__ int   g_s0[NB];
__device__ float g_cq[2][NB][ND];
__device__ int   g_cnt1, g_cnt2, g_nsup;
__device__ int   g_list1[MAX1];
__device__ int   g_list2[MAX2];
__device__ int   g_sup[SUPN];          // packed: e | (b << 17)
__device__ int   g_hkey[HSZ];
__device__ int   g_hval[HSZ];          // -> support index
__device__ float g_hep[SUPN];
__device__ float g_hhist[SUPN][ND];
__device__ int   g_h2key[HSZ2];
__device__ float g_h2ep[HSZ2];
// barrier state (self-consistent across launches: cnt returns to 0, gen monotonic)
__device__ unsigned g_bar_cnt;
__device__ unsigned g_bar_gen;

__device__ __forceinline__ float sigm(float x) { return 1.0f / (1.0f + expf(-x)); }

__device__ __forceinline__ void grid_sync() {
    __syncthreads();
    if (threadIdx.x == 0) {
        unsigned gen = __ldcg(&g_bar_gen);
        __threadfence();
        unsigned arrived = atomicAdd(&g_bar_cnt, 1) + 1;
        if (arrived == NBLK) {
            g_bar_cnt = 0;
            __threadfence();
            atomicAdd(&g_bar_gen, 1);
        } else {
            while (__ldcg(&g_bar_gen) == gen) __nanosleep(64);
        }
        __threadfence();
    }
    __syncthreads();
}

// group-local barrier: 64 threads (2 warps), group g uses named barrier g+1
#define GSYNC(g) asm volatile("bar.sync %0, 64;" :: "r"((g) + 1) : "memory")

// insert key, return support index (allocating if new). Never expected full.
__device__ __forceinline__ int hinsert1(int key, int e, int b) {
    unsigned h = ((unsigned)key * 2654435761u) & (HSZ - 1);
    for (;;) {
        int prev = atomicCAS(&g_hkey[h], -1, key);
        if (prev == -1) {
            int sidx = atomicAdd(&g_nsup, 1);
            if (sidx < SUPN) g_sup[sidx] = e | (b << 17);
            atomicExch(&g_hval[h], sidx);
            return sidx;
        }
        if (prev == key) {
            int v;
            while ((v = __ldcg(&g_hval[h])) < 0) {}
            return v;
        }
        h = (h + 1) & (HSZ - 1);
    }
}

__device__ __forceinline__ int hfind1(int key) {
    unsigned h = ((unsigned)key * 2654435761u) & (HSZ - 1);
    for (;;) {
        int k = __ldcg(&g_hkey[h]);
        if (k == key) return __ldcg(&g_hval[h]);
        if (k == -1) return -1;
        h = (h + 1) & (HSZ - 1);
    }
}

__device__ __forceinline__ int hinsert2(int key) {
    unsigned h = ((unsigned)key * 2654435761u) & (HSZ2 - 1);
    for (;;) {
        int prev = atomicCAS(&g_h2key[h], -1, key);
        if (prev == -1 || prev == key) return (int)h;
        h = (h + 1) & (HSZ2 - 1);
    }
}

__global__ __launch_bounds__(NTHR, 1)
void k_fused(const float4* __restrict__ start4, const float* __restrict__ rel_emb,
             const float* __restrict__ W_step, const float* __restrict__ b_step,
             const float* __restrict__ w_ih, const float* __restrict__ w_hh,
             const float* __restrict__ b_ih, const float* __restrict__ b_hh,
             const float* __restrict__ w_cls, const float* __restrict__ b_cls,
             const int* __restrict__ query, const int* __restrict__ kb,
             float* __restrict__ out)
{
    const int tid = blockIdx.x * NTHR + threadIdx.x;
    const int g   = threadIdx.x >> 6;       // group in block (0..3)
    const int d   = threadIdx.x & 63;       // feature lane
    const int gg  = blockIdx.x * 4 + g;     // global group id
    const int NG  = NBLK * 4;

    __shared__ float s_rf[4][ND], s_h[4][ND], s_red[4][ND];
    __shared__ int   s_slot[4];
    __shared__ float s_objp[4];

    // ---------------- Phase A: init ----------------
    {
        float4* out4 = (float4*)out;
        const int n4 = (NB * NE) / 4;
        for (int i = tid; i < n4; i += NTH_TOT) {
            out4[i] = make_float4(0.f, 0.f, 0.f, 0.f);
            float4 s = start4[i];
            if (s.x != 0.f || s.y != 0.f || s.z != 0.f || s.w != 0.f) {
                int b  = i / (NE / 4);
                int p0 = i * 4 - b * NE;
                if (s.x != 0.f) g_s0[b] = p0;
                if (s.y != 0.f) g_s0[b] = p0 + 1;
                if (s.z != 0.f) g_s0[b] = p0 + 2;
                if (s.w != 0.f) g_s0[b] = p0 + 3;
            }
        }
        if (tid < HSZ)  { g_hkey[tid] = -1; g_hval[tid] = -1; }
        if (tid < HSZ2) { g_h2key[tid] = -1; g_h2ep[tid] = 0.f; }
        if (tid < SUPN) g_hep[tid] = 0.f;
        {
            float4* hh4 = (float4*)g_hhist;
            const int nh4 = SUPN * ND / 4;
            for (int i = tid; i < nh4; i += NTH_TOT)
                hh4[i] = make_float4(0.f, 0.f, 0.f, 0.f);
        }
        if (tid == 0) { g_cnt1 = 0; g_cnt2 = 0; g_nsup = 0; }

        // block 0: compute cq[step][b][:] = tanh(rel_emb[query[b]] @ W_step[step] + b_step[step])
        if (blockIdx.x == 0) {
            for (int o = threadIdx.x; o < 2 * NB * ND; o += NTHR) {
                int step = o >> 8, rem = o & 255, b = rem >> 6, j = rem & 63;
                int q = __ldcg(&query[b]);
                float acc = b_step[step * ND + j];
                const float* re = rel_emb + q * ND;
                const float* W  = W_step + step * ND * ND + j;
                #pragma unroll 8
                for (int i = 0; i < ND; i++) acc += re[i] * W[i * ND];
                g_cq[step][b][j] = tanhf(acc);
            }
        }
    }
    grid_sync();

    // ---------------- Phase B: hop-1 collect (4 triples / thread via int4) ----------------
    {
        int a0 = __ldcg(&g_s0[0]), a1 = __ldcg(&g_s0[1]);
        int a2 = __ldcg(&g_s0[2]), a3 = __ldcg(&g_s0[3]);
        const int4* kb4 = (const int4*)kb;
        const int nchunk = NT / 4;
        for (int c = tid; c < nchunk; c += NTH_TOT) {
            int4 v0 = kb4[3 * c], v1 = kb4[3 * c + 1], v2 = kb4[3 * c + 2];
            int ss[4] = { v0.x, v0.w, v1.z, v2.y };
            #pragma unroll
            for (int j = 0; j < 4; j++) {
                int s = ss[j];
                unsigned m = (unsigned)(s == a0) | ((unsigned)(s == a1) << 1)
                           | ((unsigned)(s == a2) << 2) | ((unsigned)(s == a3) << 3);
                while (m) {
                    int b = __ffs(m) - 1; m &= m - 1;
                    int i = atomicAdd(&g_cnt1, 1);
                    if (i < MAX1) g_list1[i] = (4 * c + j) * 4 + b;
                }
            }
        }
    }
    grid_sync();

    // ---------------- Phase C: hop-1 GRU (h = 0) per entry, one 64-thread group each ----------------
    {
        int n1 = min(__ldcg(&g_cnt1), MAX1);
        for (int i = gg; i < n1; i += NG) {
            int code = __ldcg(&g_list1[i]);
            int t = code >> 2, b = code & 3;
            int e = __ldcg(&kb[3 * t + 1]), rid = __ldcg(&kb[3 * t + 2]);

            s_rf[g][d] = rel_emb[rid * ND + d];
            GSYNC(g);

            float xr = b_ih[d], xz = b_ih[ND + d], xn = b_ih[2 * ND + d];
            const float* wr = w_ih + d * ND;
            const float* wz = w_ih + (ND + d) * ND;
            const float* wn = w_ih + (2 * ND + d) * ND;
            #pragma unroll 8
            for (int k = 0; k < ND; k++) {
                float f = s_rf[g][k];
                xr += f * wr[k]; xz += f * wz[k]; xn += f * wn[k];
            }
            float r  = sigm(xr + b_hh[d]);
            float z  = sigm(xz + b_hh[ND + d]);
            float nn = tanhf(xn + r * b_hh[2 * ND + d]);
            float trans = (1.0f - z) * nn;                 // h = 0

            s_red[g][d] = trans * __ldcg(&g_cq[0][b][d]) * w_cls[d];
            GSYNC(g);
            if (d < 32) {
                float v = s_red[g][d] + s_red[g][d + 32];
                #pragma unroll
                for (int off = 16; off > 0; off >>= 1)
                    v += __shfl_down_sync(0xffffffffu, v, off);
                if (d == 0) {
                    float p = sigm(v + b_cls[0]);          // obj_p = 1 * p
                    int sidx = hinsert1(b * NE + e, e, b);
                    s_slot[g] = sidx; s_objp[g] = p;
                    atomicAdd(&g_hep[sidx], p);
                }
            }
            GSYNC(g);
            atomicAdd(&g_hhist[s_slot[g]][d], trans * s_objp[g]);
            GSYNC(g);
        }
    }
    grid_sync();

    // ---------------- Phase D: hop-2 collect (compare subjects vs support list) ----------------
    {
        __shared__ int sh_sup[SUPN];
        __shared__ int sh_ns;
        if (threadIdx.x == 0) sh_ns = min(__ldcg(&g_nsup), SUPN);
        __syncthreads();
        int ns = sh_ns;
        for (int j = threadIdx.x; j < ns; j += NTHR) sh_sup[j] = __ldcg(&g_sup[j]);
        __syncthreads();

        const int4* kb4 = (const int4*)kb;
        const int nchunk = NT / 4;
        for (int c = tid; c < nchunk; c += NTH_TOT) {
            int4 v0 = kb4[3 * c], v1 = kb4[3 * c + 1], v2 = kb4[3 * c + 2];
            int ss[4] = { v0.x, v0.w, v1.z, v2.y };
            #pragma unroll
            for (int j = 0; j < 4; j++) {
                int s = ss[j];
                for (int k = 0; k < ns; k++) {
                    int p = sh_sup[k];
                    if ((p & 0x1FFFF) == s) {
                        int b = p >> 17;
                        int i = atomicAdd(&g_cnt2, 1);
                        if (i < MAX2) g_list2[i] = (4 * c + j) * 4 + b;
                    }
                }
            }
        }
    }
    grid_sync();

    // ---------------- Phase E: hop-2 full GRU per entry ----------------
    {
        int n2 = min(__ldcg(&g_cnt2), MAX2);
        for (int i = gg; i < n2; i += NG) {
            int code = __ldcg(&g_list2[i]);
            int t = code >> 2, b = code & 3;
            int s = __ldcg(&kb[3 * t]), e = __ldcg(&kb[3 * t + 1]), rid = __ldcg(&kb[3 * t + 2]);

            if (d == 0) s_slot[g] = hfind1(b * NE + s);   // guaranteed found
            GSYNC(g);
            int sidx = s_slot[g];
            float ep = __ldcg(&g_hep[sidx]);
            s_h[g][d]  = __ldcg(&g_hhist[sidx][d]) / (ep + EPSV);
            s_rf[g][d] = rel_emb[rid * ND + d];
            GSYNC(g);

            float xr = b_ih[d], xz = b_ih[ND + d], xn = b_ih[2 * ND + d];
            float hr = b_hh[d], hz = b_hh[ND + d], hn = b_hh[2 * ND + d];
            const float* wir = w_ih + d * ND;
            const float* wiz = w_ih + (ND + d) * ND;
            const float* win = w_ih + (2 * ND + d) * ND;
            const float* whr = w_hh + d * ND;
            const float* whz = w_hh + (ND + d) * ND;
            const float* whn = w_hh + (2 * ND + d) * ND;
            #pragma unroll 4
            for (int k = 0; k < ND; k++) {
                float f = s_rf[g][k], hh = s_h[g][k];
                xr += f * wir[k]; xz += f * wiz[k]; xn += f * win[k];
                hr += hh * whr[k]; hz += hh * whz[k]; hn += hh * whn[k];
            }
            float r  = sigm(xr + hr);
            float z  = sigm(xz + hz);
            float nn = tanhf(xn + r * hn);
            float trans = (1.0f - z) * nn + z * s_h[g][d];

            s_red[g][d] = trans * __ldcg(&g_cq[1][b][d]) * w_cls[d];
            GSYNC(g);
            if (d < 32) {
                float v = s_red[g][d] + s_red[g][d + 32];
                #pragma unroll
                for (int off = 16; off > 0; off >>= 1)
                    v += __shfl_down_sync(0xffffffffu, v, off);
                if (d == 0) {
                    float p = sigm(v + b_cls[0]);
                    float last0 = fminf(ep, 1.0f);         // = obj_ep / zden
                    int sl2 = hinsert2(b * NE + e);
                    atomicAdd(&g_h2ep[sl2], last0 * p);
                }
            }
            GSYNC(g);
        }
    }
    grid_sync();

    // ---------------- Phase F: scatter hash2 -> out with clamp ----------------
    if (tid < HSZ2) {
        int k = __ldcg(&g_h2key[tid]);
        if (k >= 0) out[k] = fminf(__ldcg(&g_h2ep[tid]), 1.0f);
    }
}

extern "C" void kernel_launch(void* const* d_in, const int* in_sizes, int n_in,
                              void* d_out, int out_size)
{
    const float* start   = (const float*)d_in[0];
    const float* rel_emb = (const float*)d_in[1];
    const float* W_step  = (const float*)d_in[2];
    const float* b_step  = (const float*)d_in[3];
    const float* w_ih    = (const float*)d_in[4];
    const float* w_hh    = (const float*)d_in[5];
    const float* b_ih    = (const float*)d_in[6];
    const float* b_hh    = (const float*)d_in[7];
    const float* w_cls   = (const float*)d_in[8];
    const float* b_cls   = (const float*)d_in[9];
    const int*   query   = (const int*)d_in[10];
    const int*   kb      = (const int*)d_in[11];
    float* out = (float*)d_out;

    k_fused<<<NBLK, NTHR>>>((const float4*)start, rel_emb, W_step, b_step,
                            w_ih, w_hh, b_ih, b_hh, w_cls, b_cls, query, kb, out);
}